// round 13
// baseline (speedup 1.0000x reference)
#include <cuda_runtime.h>
#include <cuda_bf16.h>
#include <math.h>

// Quantized softmax (SoftmaxBernoulli2): rows of 2048 int32 in [-128,127].
// LUT[q] = clip(round(exp((q-255)*is)/es),0,255); idx = x - rowmax + 255 (in [0,255]);
// out = LUT[idx] / sum_row(LUT[idx]) as fp32.
//
// R13 = R12 (speculative xmax=127 gather, byte-addressed conflict-free LUT, fused
// table build, 8 CTAs/SM) + thread-private cp.async staging: each thread stages
// exactly the 32B it reads -> wait_group replaces barrier A; refill of own bytes
// has no cross-thread hazard -> ONE __syncthreads per row (publish partials),
// parity-double-buffered partial arrays.

#define ROW   2048
#define TPB   256
#define VPT   8
#define NWARP (TPB / 32)

__device__ __forceinline__ void cp_async16(void* smem, const void* gmem) {
    unsigned saddr = (unsigned)__cvta_generic_to_shared(smem);
    asm volatile("cp.async.cg.shared.global [%0], [%1], 16;\n"
                 :: "r"(saddr), "l"(gmem) : "memory");
}
#define CP_COMMIT() asm volatile("cp.async.commit_group;\n" ::: "memory")
#define CP_WAIT1()  asm volatile("cp.async.wait_group 1;\n" ::: "memory")

__global__ __launch_bounds__(TPB, 8) void softmax_bernoulli2_kernel(
    const int* __restrict__ x, float* __restrict__ out,
    const float* __restrict__ input_scale, const float* __restrict__ exp_scale,
    int n_rows) {
    __shared__ unsigned s_tab[64 * 32];   // replicated packed LUT; gathered as bytes
    __shared__ int s_buf[2][ROW];         // double-buffered rows; bytes thread-private
    __shared__ int s_tmp[256];            // scalar table staging
    __shared__ double s_r2[9];            // [0..7]=r^(2^j), [8]=1/exp_scale
    __shared__ int s_max[2][NWARP];       // parity-buffered partials
    __shared__ int s_sum[2][NWARP];
    __shared__ int s_sum2[NWARP];         // cold-path redo sums

    const int tid  = threadIdx.x;
    const int lane = tid & 31;
    const int warp = tid >> 5;

    const long long stride = gridDim.x;   // grid clamped to <= n_rows
    long long row = blockIdx.x;

    // ---- prime both buffers FIRST (thread-private: stage exactly own 32B) ----
    {
        const int* g0 = x + row * ROW + tid * 8;
        cp_async16(&s_buf[0][tid * 8], g0);
        cp_async16(&s_buf[0][tid * 8 + 4], g0 + 4);
        CP_COMMIT();
        long long r1 = row + stride;
        if (r1 >= n_rows) r1 = row;       // clamped dummy
        const int* g1 = x + r1 * ROW + tid * 8;
        cp_async16(&s_buf[1][tid * 8], g1);
        cp_async16(&s_buf[1][tid * 8 + 4], g1 + 4);
        CP_COMMIT();
    }

    // ---- table build (overlaps priming flight): exp((q-255)*is) = r^(255-q) ----
    if (tid == 0) {
        double r = exp(-(double)input_scale[0]);  // ONE double exp per CTA
        double p = r;
        #pragma unroll
        for (int j = 0; j < 8; j++) { s_r2[j] = p; p = p * p; }
        s_r2[8] = 1.0 / (double)exp_scale[0];
    }
    __syncthreads();
    {
        int k = 255 - tid;                // exponent, 0..255
        double t = s_r2[8];               // t = r^k / es
        #pragma unroll
        for (int j = 0; j < 8; j++) if ((k >> j) & 1) t *= s_r2[j];
        double r = nearbyint(t);          // half-even, matches jnp.round
        r = fmin(fmax(r, 0.0), 255.0);
        s_tmp[tid] = (int)r;
    }
    __syncthreads();
    #pragma unroll
    for (int i = tid; i < 64 * 32; i += TPB) {
        int w4 = (i >> 5) << 2;
        s_tab[i] = (unsigned)s_tmp[w4] | ((unsigned)s_tmp[w4 + 1] << 8) |
                   ((unsigned)s_tmp[w4 + 2] << 16) | ((unsigned)s_tmp[w4 + 3] << 24);
    }
    __syncthreads();                      // one-time fence: s_tab ready for gathers

    // Byte view: entry idx at ((idx>>2)<<7) + (lane<<2) + (idx&3); bits[6:2]==lane
    // -> bank == lane, conflict-free LDS.U8.
    const unsigned char* tabB =
        reinterpret_cast<const unsigned char*>(s_tab) + (lane << 2);

    int p = 0;
    int par = 0;
    for (; row < n_rows; row += stride, p ^= 1, par ^= 1) {
        // Own bytes visible once <=1 group pending — no barrier.
        CP_WAIT1();
        int4 a = *reinterpret_cast<const int4*>(&s_buf[p][tid * 8]);
        int4 b = *reinterpret_cast<const int4*>(&s_buf[p][tid * 8 + 4]);
        int v[VPT] = {a.x, a.y, a.z, a.w, b.x, b.y, b.z, b.w};

        // ---- max chain (off critical path thanks to speculation) ----
        int m = v[0];
        #pragma unroll
        for (int k = 1; k < VPT; k++) m = max(m, v[k]);
        #pragma unroll
        for (int o = 16; o > 0; o >>= 1) m = max(m, __shfl_xor_sync(0xFFFFFFFFu, m, o));
        if (lane == 0) s_max[par][warp] = m;

        // ---- speculative gather assuming xmax == 127 (c = 128) + sum chain ----
        int e[VPT];
        int sum = 0;
        #pragma unroll
        for (int k = 0; k < VPT; k++) {
            unsigned idx = (unsigned)(v[k] + 128);            // in [0,255]
            e[k] = (int)tabB[((idx >> 2) << 7) + (idx & 3u)]; // LDS.U8, bank==lane
            sum += e[k];
        }
        #pragma unroll
        for (int o = 16; o > 0; o >>= 1) sum += __shfl_xor_sync(0xFFFFFFFFu, sum, o);
        if (lane == 0) s_sum[par][warp] = sum;

        // ---- refill own bytes of freed buffer with row + 2*stride (no hazard) ----
        {
            long long pr = row + 2 * stride;
            if (pr >= n_rows) pr = row;   // clamped dummy
            const int* g = x + pr * ROW + tid * 8;
            cp_async16(&s_buf[p][tid * 8], g);
            cp_async16(&s_buf[p][tid * 8 + 4], g + 4);
            CP_COMMIT();
        }

        __syncthreads();                  // THE barrier: max + spec sum published

        int xmax = s_max[par][0];
        #pragma unroll
        for (int w = 1; w < NWARP; w++) xmax = max(xmax, s_max[par][w]);

        int total;
        if (xmax == 127) {                // hot path (~99.97% of rows)
            total = s_sum[par][0];
            #pragma unroll
            for (int w = 1; w < NWARP; w++) total += s_sum[par][w];
        } else {                          // cold path: uniform branch, always correct
            const int c = 255 - xmax;
            int sum2 = 0;
            #pragma unroll
            for (int k = 0; k < VPT; k++) {
                unsigned idx = (unsigned)(v[k] + c);          // in [0,255]
                e[k] = (int)tabB[((idx >> 2) << 7) + (idx & 3u)];
                sum2 += e[k];
            }
            #pragma unroll
            for (int o = 16; o > 0; o >>= 1) sum2 += __shfl_xor_sync(0xFFFFFFFFu, sum2, o);
            if (lane == 0) s_sum2[warp] = sum2;
            __syncthreads();
            total = s_sum2[0];
            #pragma unroll
            for (int w = 1; w < NWARP; w++) total += s_sum2[w];
            __syncthreads();              // protect s_sum2 reuse (cold path only)
        }

        const float inv = 1.0f / (float)total;

        float4 o0, o1;
        o0.x = (float)e[0] * inv; o0.y = (float)e[1] * inv;
        o0.z = (float)e[2] * inv; o0.w = (float)e[3] * inv;
        o1.x = (float)e[4] * inv; o1.y = (float)e[5] * inv;
        o1.z = (float)e[6] * inv; o1.w = (float)e[7] * inv;
        float4* op = reinterpret_cast<float4*>(out + row * ROW) + tid * 2;
        __stcs(op, o0);                   // streaming stores: no reuse
        __stcs(op + 1, o1);
    }
}

extern "C" void kernel_launch(void* const* d_in, const int* in_sizes, int n_in,
                              void* d_out, int out_size) {
    const int* x             = (const int*)d_in[0];
    const float* input_scale = (const float*)d_in[1];
    const float* exp_scale   = (const float*)d_in[2];
    float* out = (float*)d_out;

    const int n_rows = in_sizes[0] / ROW;

    int nblocks = 152 * 8;                // 8 CTAs/SM (~26KB smem, ~32 regs)
    if (nblocks > n_rows) nblocks = n_rows;

    softmax_bernoulli2_kernel<<<nblocks, TPB>>>(x, out, input_scale, exp_scale, n_rows);
}

// round 14
// speedup vs baseline: 1.0650x; 1.0650x over previous
#include <cuda_runtime.h>
#include <cuda_bf16.h>
#include <math.h>

// Quantized softmax (SoftmaxBernoulli2): rows of 2048 int32 in [-128,127].
// LUT[q] = clip(round(exp((q-255)*is)/es),0,255); idx = x - rowmax + 255 (in [0,255]);
// out = LUT[idx] / sum_row(LUT[idx]) as fp32.
//
// R14 = R12 frame (barrier-A cp.async double buffering — the shape that benches
// best under graph replay; speculative xmax=127 gather; byte-addressed
// conflict-free LUT; fused table build; 8 CTAs/SM) with the hot-path max
// shfl-chain replaced by ONE __any_sync(v==127) vote (xmax==127 iff any element
// ==127). True max is computed only on the rare cold path. Cuts ~25% of hot-path
// MIO ops (SHFL shares MIO with the critical LDS gather stream).

#define ROW   2048
#define TPB   256
#define VPT   8
#define NWARP (TPB / 32)

__device__ __forceinline__ void cp_async16(void* smem, const void* gmem) {
    unsigned saddr = (unsigned)__cvta_generic_to_shared(smem);
    asm volatile("cp.async.cg.shared.global [%0], [%1], 16;\n"
                 :: "r"(saddr), "l"(gmem) : "memory");
}
#define CP_COMMIT() asm volatile("cp.async.commit_group;\n" ::: "memory")
#define CP_WAIT1()  asm volatile("cp.async.wait_group 1;\n" ::: "memory")

__global__ __launch_bounds__(TPB, 8) void softmax_bernoulli2_kernel(
    const int* __restrict__ x, float* __restrict__ out,
    const float* __restrict__ input_scale, const float* __restrict__ exp_scale,
    int n_rows) {
    __shared__ unsigned s_tab[64 * 32];   // replicated packed LUT; gathered as bytes
    __shared__ int s_buf[2][ROW];         // double-buffered staged rows
    __shared__ int s_tmp[256];            // scalar table staging
    __shared__ double s_r2[9];            // [0..7]=r^(2^j), [8]=1/exp_scale
    __shared__ int s_flag[NWARP];         // per-warp "has 127" flags
    __shared__ int s_sum[NWARP];          // spec sum partials
    __shared__ int s_red[NWARP];          // cold-path scratch (max, then redo sums)

    const int tid  = threadIdx.x;
    const int lane = tid & 31;
    const int warp = tid >> 5;

    const long long stride = gridDim.x;   // grid clamped to <= n_rows
    long long row = blockIdx.x;

    // ---- issue priming loads FIRST so they fly during the table build ----
    {
        const int* s0 = x + row * ROW + tid * 4;
        cp_async16(&s_buf[0][tid * 4], s0);
        cp_async16(&s_buf[0][1024 + tid * 4], s0 + 1024);
        CP_COMMIT();
        long long r1 = row + stride;
        if (r1 >= n_rows) r1 = row;       // clamped dummy
        const int* s1 = x + r1 * ROW + tid * 4;
        cp_async16(&s_buf[1][tid * 4], s1);
        cp_async16(&s_buf[1][1024 + tid * 4], s1 + 1024);
        CP_COMMIT();
    }

    // ---- table build: exp((q-255)*is) = r^(255-q), binary exponentiation ----
    if (tid == 0) {
        double r = exp(-(double)input_scale[0]);  // ONE double exp per CTA
        double p = r;
        #pragma unroll
        for (int j = 0; j < 8; j++) { s_r2[j] = p; p = p * p; }
        s_r2[8] = 1.0 / (double)exp_scale[0];
    }
    __syncthreads();
    {
        int k = 255 - tid;                // exponent, 0..255
        double t = s_r2[8];               // t = r^k / es
        #pragma unroll
        for (int j = 0; j < 8; j++) if ((k >> j) & 1) t *= s_r2[j];
        double r = nearbyint(t);          // half-even, matches jnp.round
        r = fmin(fmax(r, 0.0), 255.0);
        s_tmp[tid] = (int)r;
    }
    __syncthreads();
    #pragma unroll
    for (int i = tid; i < 64 * 32; i += TPB) {
        int w4 = (i >> 5) << 2;
        s_tab[i] = (unsigned)s_tmp[w4] | ((unsigned)s_tmp[w4 + 1] << 8) |
                   ((unsigned)s_tmp[w4 + 2] << 16) | ((unsigned)s_tmp[w4 + 3] << 24);
    }
    // (barrier A below fences s_tab before first gather)

    // Byte view: entry idx at ((idx>>2)<<7) + (lane<<2) + (idx&3); bits[6:2]==lane
    // -> bank == lane, conflict-free LDS.U8.
    const unsigned char* tabB =
        reinterpret_cast<const unsigned char*>(s_tab) + (lane << 2);

    int p = 0;
    for (; row < n_rows; row += stride, p ^= 1) {
        CP_WAIT1();
        __syncthreads();                  // barrier A: buf[p] ready CTA-wide (+ LUT fence)

        int4 a = *reinterpret_cast<const int4*>(&s_buf[p][tid * 8]);
        int4 b = *reinterpret_cast<const int4*>(&s_buf[p][tid * 8 + 4]);
        int v[VPT] = {a.x, a.y, a.z, a.w, b.x, b.y, b.z, b.w};

        // ---- speculation check: xmax==127 iff any element ==127 (1 VOTE, no shfls) --
        int m = v[0];
        #pragma unroll
        for (int k = 1; k < VPT; k++) m = max(m, v[k]);
        int has127 = __any_sync(0xFFFFFFFFu, m == 127);
        if (lane == 0) s_flag[warp] = has127;

        // ---- speculative gather assuming xmax == 127 (c = 128) + sum chain ----
        int e[VPT];
        int sum = 0;
        #pragma unroll
        for (int k = 0; k < VPT; k++) {
            unsigned idx = (unsigned)(v[k] + 128);            // in [0,255]
            e[k] = (int)tabB[((idx >> 2) << 7) + (idx & 3u)]; // LDS.U8, bank==lane
            sum += e[k];
        }
        #pragma unroll
        for (int o = 16; o > 0; o >>= 1) sum += __shfl_xor_sync(0xFFFFFFFFu, sum, o);
        if (lane == 0) s_sum[warp] = sum;

        // ---- refill freed buffer with row + 2*stride (clamped) ----
        {
            long long pr = row + 2 * stride;
            if (pr >= n_rows) pr = row;   // clamped dummy
            const int* sp = x + pr * ROW + tid * 4;
            cp_async16(&s_buf[p][tid * 4], sp);
            cp_async16(&s_buf[p][1024 + tid * 4], sp + 1024);
            CP_COMMIT();
        }

        __syncthreads();                  // barrier B: flags + spec sums published

        int anyflag = s_flag[0];
        #pragma unroll
        for (int w = 1; w < NWARP; w++) anyflag |= s_flag[w];

        int total;
        if (anyflag) {                    // hot path (~99.97% of rows)
            total = s_sum[0];
            #pragma unroll
            for (int w = 1; w < NWARP; w++) total += s_sum[w];
        } else {                          // cold path: block-uniform, always correct
            // true block max (m still holds thread-local max)
            #pragma unroll
            for (int o = 16; o > 0; o >>= 1) m = max(m, __shfl_xor_sync(0xFFFFFFFFu, m, o));
            if (lane == 0) s_red[warp] = m;
            __syncthreads();
            int xmax = s_red[0];
            #pragma unroll
            for (int w = 1; w < NWARP; w++) xmax = max(xmax, s_red[w]);
            const int c = 255 - xmax;
            int sum2 = 0;
            #pragma unroll
            for (int k = 0; k < VPT; k++) {
                unsigned idx = (unsigned)(v[k] + c);          // in [0,255]
                e[k] = (int)tabB[((idx >> 2) << 7) + (idx & 3u)];
                sum2 += e[k];
            }
            #pragma unroll
            for (int o = 16; o > 0; o >>= 1) sum2 += __shfl_xor_sync(0xFFFFFFFFu, sum2, o);
            __syncthreads();              // all reads of s_red done before overwrite
            if (lane == 0) s_red[warp] = sum2;
            __syncthreads();
            total = s_red[0];
            #pragma unroll
            for (int w = 1; w < NWARP; w++) total += s_red[w];
        }

        const float inv = 1.0f / (float)total;

        float4 o0, o1;
        o0.x = (float)e[0] * inv; o0.y = (float)e[1] * inv;
        o0.z = (float)e[2] * inv; o0.w = (float)e[3] * inv;
        o1.x = (float)e[4] * inv; o1.y = (float)e[5] * inv;
        o1.z = (float)e[6] * inv; o1.w = (float)e[7] * inv;
        float4* op = reinterpret_cast<float4*>(out + row * ROW) + tid * 2;
        __stcs(op, o0);                   // streaming stores: no reuse
        __stcs(op + 1, o1);
    }
}

extern "C" void kernel_launch(void* const* d_in, const int* in_sizes, int n_in,
                              void* d_out, int out_size) {
    const int* x             = (const int*)d_in[0];
    const float* input_scale = (const float*)d_in[1];
    const float* exp_scale   = (const float*)d_in[2];
    float* out = (float*)d_out;

    const int n_rows = in_sizes[0] / ROW;

    int nblocks = 152 * 8;                // 8 CTAs/SM (~26KB smem, ~32 regs)
    if (nblocks > n_rows) nblocks = n_rows;

    softmax_bernoulli2_kernel<<<nblocks, TPB>>>(x, out, input_scale, exp_scale, n_rows);
}